// round 12
// baseline (speedup 1.0000x reference)
#include <cuda_runtime.h>
#include <cstdint>

__device__ float g_h[134217728];   // [E*B][y][x][128co]
__device__ float g_xnhwc[8388608]; // [B][y][x][64ci]
__device__ float g_y[16777216];    // [B][y][x][128co]
__device__ float g_w1p[589824];    // [tap][ci][e][co]  (R9 layout)
__device__ float g_w2p[1179648];   // [e][tap][ci128][co]
__device__ float g_wrp[65536];     // [e][ci][co]
__device__ float g_gates[4096];
__device__ float g_p1[8192], g_p2[8192];   // per (b,tile,group) partials

#define CPC  asm volatile("cp.async.commit_group;\n" ::: "memory")
#define CPW0 asm volatile("cp.async.wait_group 0;\n" ::: "memory")
#define CPW1 asm volatile("cp.async.wait_group 1;\n" ::: "memory")

__device__ __forceinline__ uint32_t s2u(const void* p) {
    return (uint32_t)__cvta_generic_to_shared(p);
}
__device__ __forceinline__ void cpa(uint32_t d, const void* s, bool v) {
    int sz = v ? 16 : 0;
    asm volatile("cp.async.cg.shared.global [%0],[%1],16,%2;\n" :: "r"(d), "l"(s), "r"(sz));
}
__device__ __forceinline__ float rna(float x) {
    uint32_t u; asm("cvt.rna.tf32.f32 %0,%1;" : "=r"(u) : "f"(x));
    return __uint_as_float(u);
}
__device__ __forceinline__ void mma8(float* c, const uint32_t* a, const uint32_t* b) {
    asm volatile("mma.sync.aligned.m16n8k8.row.col.f32.tf32.tf32.f32 "
        "{%0,%1,%2,%3},{%4,%5,%6,%7},{%8,%9},{%0,%1,%2,%3};"
        : "+f"(c[0]), "+f"(c[1]), "+f"(c[2]), "+f"(c[3])
        : "r"(a[0]), "r"(a[1]), "r"(a[2]), "r"(a[3]), "r"(b[0]), "r"(b[1]));
}

// K=64 of a (pix)x(128ch) GEMM, MT m-tiles of 16 px per warp.
// A pixel-major [(p>>4)*ARS+(p&15)][ASTR], B [k][136].
template<int ARS, int ASTR, int MT>
__device__ __forceinline__ void ksteps8(const float* As, int aBase, const float* Ws,
                                        int mbase, int nbase, int lane, float acc[MT][8][4]) {
#pragma unroll
    for (int k0 = 0; k0 < 64; k0 += 8) {
        uint32_t a[MT][4], bq[8][2];
        int kr = k0 + (lane & 3);
#pragma unroll
        for (int mt = 0; mt < MT; mt++) {
            int p0 = mbase + mt * 16 + (lane >> 2), p1 = p0 + 8;
            int ad0 = aBase + ((p0 >> 4) * ARS + (p0 & 15)) * ASTR;
            int ad1 = aBase + ((p1 >> 4) * ARS + (p1 & 15)) * ASTR;
            a[mt][0] = __float_as_uint(As[ad0 + kr]);
            a[mt][1] = __float_as_uint(As[ad1 + kr]);
            a[mt][2] = __float_as_uint(As[ad0 + kr + 4]);
            a[mt][3] = __float_as_uint(As[ad1 + kr + 4]);
        }
#pragma unroll
        for (int nt = 0; nt < 8; nt++) {
            int n = nbase + nt * 8 + (lane >> 2);
            bq[nt][0] = __float_as_uint(Ws[kr * 136 + n]);
            bq[nt][1] = __float_as_uint(Ws[(kr + 4) * 136 + n]);
        }
#pragma unroll
        for (int mt = 0; mt < MT; mt++)
#pragma unroll
            for (int nt = 0; nt < 8; nt++) mma8(acc[mt][nt], a[mt], bq[nt]);
    }
}

// ---------------- router ----------------
__global__ void router_kernel(const float* __restrict__ x,
                              const float* __restrict__ Rw1, const float* __restrict__ Rb1,
                              const float* __restrict__ Rw2, const float* __restrict__ Rb2) {
    __shared__ float gf[80], hb[128], lg[8];
    int pid = blockIdx.x, b = pid >> 6, pr = (pid >> 3) & 7, pc = pid & 7;
    int t = threadIdx.x;
    if (t < 64) {
        const float* xp = x + ((size_t)(b * 64 + t) * 128 + pr * 16) * 128 + pc * 16;
        float s = 0.f;
        for (int yy = 0; yy < 16; yy++)
#pragma unroll
            for (int xx = 0; xx < 16; xx++) s += xp[yy * 128 + xx];
        gf[t] = s * (1.f / 256.f);
    } else if (t < 80) {
        int i = t - 64, j = i & 3, kind = i >> 2;
        float fr = 3.14159265358979323846f * (float)(1 << j);
        float co = (kind < 2) ? ((pr + 0.5f) / 8.f) : ((pc + 0.5f) / 8.f);
        float a = co * fr;
        gf[t] = (kind & 1) ? cosf(a) : sinf(a);
    }
    __syncthreads();
    float acc = Rb1[t];
    for (int c = 0; c < 80; c++) acc += gf[c] * Rw1[c * 128 + t];
    hb[t] = fmaxf(acc, 0.f);
    __syncthreads();
    if (t < 8) {
        float l = Rb2[t];
        for (int d = 0; d < 128; d++) l += hb[d] * Rw2[d * 8 + t];
        lg[t] = l;
    }
    __syncthreads();
    if (t == 0) {
        float m = lg[0];
        for (int i = 1; i < 8; i++) m = fmaxf(m, lg[i]);
        float ex[8], ss = 0.f;
        for (int i = 0; i < 8; i++) { ex[i] = expf(lg[i] - m); ss += ex[i]; }
        for (int i = 0; i < 8; i++) g_gates[pid * 8 + i] = ex[i] / ss;
    }
}

// ---------------- x NCHW -> NHWC (tf32-rounded) ----------------
__global__ void transpose_kernel(const float* __restrict__ x) {
    __shared__ float s[64 * 129];
    int b = blockIdx.x >> 7, y = blockIdx.x & 127, t = threadIdx.x;
#pragma unroll
    for (int i = 0; i < 32; i++) {
        int idx = i * 256 + t, xx = idx & 127, c = idx >> 7;
        s[c * 129 + xx] = x[((size_t)(b * 64 + c) * 128 + y) * 128 + xx];
    }
    __syncthreads();
#pragma unroll
    for (int i = 0; i < 32; i++) {
        int idx = i * 256 + t, c = idx & 63, xx = idx >> 6;
        g_xnhwc[((b * 128 + y) * 128 + xx) * 64 + c] = rna(s[c * 129 + xx]);
    }
}

// ---------------- weight repack (tf32-rounded, R9 layouts) ----------------
__global__ void prep_kernel(const float* __restrict__ W1, const float* __restrict__ W2,
                            const float* __restrict__ Wr) {
    int idx = blockIdx.x * 256 + threadIdx.x;
    if (idx < 589824) {
        int co = idx & 127, e = (idx >> 7) & 7, ci = (idx >> 10) & 63, tap = idx >> 16;
        g_w1p[idx] = rna(W1[((e * 128 + co) * 64 + ci) * 9 + tap]);
    } else if (idx < 1769472) {
        int j = idx - 589824;
        int co = j & 127, ci = (j >> 7) & 127, r = j >> 14, tap = r % 9, e = r / 9;
        g_w2p[j] = rna(W2[((e * 128 + co) * 128 + ci) * 9 + tap]);
    } else if (idx < 1835008) {
        int j = idx - 1769472;
        int co = j & 127, ci = (j >> 7) & 63, e = j >> 13;
        g_wrp[j] = rna(Wr[(e * 128 + co) * 64 + ci]);
    }
}

// ---- conv1: 256 thr, 256-pix tile, warp 64x64, 3 w-buffers, 1 sync/tap ----
__global__ void __launch_bounds__(256, 1) conv1_kernel(const float* __restrict__ b1) {
    extern __shared__ float sm[];
    float* xs = sm;                                        // 22032
    float* wb[3] = { sm + 22032, sm + 30736, sm + 39440 }; // 8704 each
    float* bsm = sm + 48144;                               // 128
    int t = threadIdx.x, lane = t & 31, w = t >> 5;
    int tile = blockIdx.x, e = blockIdx.y, b = blockIdx.z;
    int r0 = (tile >> 3) * 16, c0 = (tile & 7) * 16;
    for (int idx = t; idx < 5184; idx += 256) {            // x halo (group)
        int pix = idx >> 4, c4 = (idx & 15) * 4;
        int rr = pix / 18, cc = pix % 18, gr = r0 + rr - 1, gc = c0 + cc - 1;
        bool v = gr >= 0 && gr < 128 && gc >= 0 && gc < 128;
        cpa(s2u(xs + pix * 68 + c4),
            g_xnhwc + ((size_t)(b * 128 + (v ? gr : 0)) * 128 + (v ? gc : 0)) * 64 + c4, v);
    }
    CPC;
#pragma unroll 1
    for (int k = 0; k < 2; k++) {                          // W0, W1 groups
        for (int idx = t; idx < 2048; idx += 256) {
            int ci = idx >> 5, c4 = (idx & 31) * 4;
            cpa(s2u(wb[k] + ci * 136 + c4), g_w1p + ((size_t)(k * 64 + ci) * 8 + e) * 128 + c4, true);
        }
        CPC;
    }
    if (t < 128) bsm[t] = b1[e * 128 + t];
    CPW1;                                                  // halo + W0 done
    __syncthreads();
    float acc[4][8][4] = {};
    int mbase = (w >> 1) * 64, nbase = (w & 1) * 64;
#pragma unroll 1
    for (int tap = 0; tap < 9; tap++) {
        if (tap > 0) __syncthreads();
        if (tap <= 6) {
            int nt_ = tap + 2;
            float* wn = wb[nt_ % 3];
            for (int idx = t; idx < 2048; idx += 256) {
                int ci = idx >> 5, c4 = (idx & 31) * 4;
                cpa(s2u(wn + ci * 136 + c4),
                    g_w1p + ((size_t)(nt_ * 64 + ci) * 8 + e) * 128 + c4, true);
            }
            CPC; CPW1;                                     // forces W(tap+1)
        } else if (tap == 7) { CPW0; }                     // forces W8
        ksteps8<18, 68, 4>(xs, ((tap / 3) * 18 + tap % 3) * 68, wb[tap % 3],
                           mbase, nbase, lane, acc);
    }
    float* hb = g_h + ((size_t)(e * 8 + b) << 21);
#pragma unroll
    for (int mt = 0; mt < 4; mt++) {
        int p0 = mbase + mt * 16 + (lane >> 2);
        int py = r0 + (p0 >> 4), px = c0 + (p0 & 15);
#pragma unroll
        for (int nt = 0; nt < 8; nt++) {
            int co = nbase + nt * 8 + (lane & 3) * 2;
            size_t base = ((size_t)py * 128 + px) * 128 + co;
            float2 v0, v1;
            v0.x = rna(fmaxf(acc[mt][nt][0] + bsm[co], 0.f));
            v0.y = rna(fmaxf(acc[mt][nt][1] + bsm[co + 1], 0.f));
            v1.x = rna(fmaxf(acc[mt][nt][2] + bsm[co], 0.f));
            v1.y = rna(fmaxf(acc[mt][nt][3] + bsm[co + 1], 0.f));
            *(float2*)(hb + base) = v0;
            *(float2*)(hb + base + 1024) = v1;
        }
    }
}

// ---- conv2: bufA(kh0) 9 taps -> bufB(kh1) 9 taps -> residual(xr in bufA);
//      3 w-buffers, 1 sync/stage, fused deterministic GN partials ----
__global__ void __launch_bounds__(256, 1) conv2_kernel(const float* __restrict__ b2,
                                                       const float* __restrict__ br) {
    extern __shared__ float sm[];
    float* bufA = sm;                                      // 12240
    float* bufB = sm + 12240;                              // 12240
    float* wb[3] = { sm + 24480, sm + 33184, sm + 41888 }; // 8704 each
    float* bsm = sm + 50592;                               // 1024
    float* gsm = sm + 51616;                               // 8
    float* wS = sm + 51624;                                // 32
    float* wQ = sm + 51656;                                // 32
    int t = threadIdx.x, lane = t & 31, w = t >> 5;
    int tile = blockIdx.x, b = blockIdx.y;
    int r0 = (tile >> 3) * 8, c0 = (tile & 7) * 16;
    for (int idx = t; idx < 1024; idx += 256) bsm[idx] = b2[idx] + br[idx];
    if (t < 8) gsm[t] = g_gates[(b * 64 + (tile >> 4) * 8 + (tile & 7)) * 8 + t];
    float comb[2][8][4] = {};
    float4 xv[8];
    int mbase = (w >> 1) * 32, nbase = (w & 1) * 64;
#pragma unroll 1
    for (int e = 0; e < 8; e++) {
        const float* hbase = g_h + ((size_t)(e * 8 + b) << 21);
        __syncthreads();                                   // all buffers free
        // prologue groups: khA, khB, W0, W1
#pragma unroll 1
        for (int kh = 0; kh < 2; kh++) {
            float* dst = kh ? bufB : bufA;
            for (int idx = t; idx < 2880; idx += 256) {
                int pix = idx >> 4, c4 = (idx & 15) * 4;
                int rr = pix / 18, cc = pix % 18, gr = r0 + rr - 1, gc = c0 + cc - 1;
                bool v = gr >= 0 && gr < 128 && gc >= 0 && gc < 128;
                cpa(s2u(dst + pix * 68 + c4),
                    hbase + ((size_t)((v ? gr : 0) * 128 + (v ? gc : 0)) * 128) + kh * 64 + c4, v);
            }
            CPC;
        }
#pragma unroll 1
        for (int k = 0; k < 2; k++) {
            const float* src = g_w2p + (size_t)((e * 9 + k) * 128) * 128;  // tap k, kh0
            for (int idx = t; idx < 2048; idx += 256) {
                int ci = idx >> 5, c4 = (idx & 31) * 4;
                cpa(s2u(wb[k] + ci * 136 + c4), src + ci * 128 + c4, true);
            }
            CPC;
        }
        CPW1;                                              // khA,khB,W0 done
        __syncthreads();
        float acc[2][8][4] = {};
#pragma unroll 1
        for (int s = 0; s < 19; s++) {
            if (s > 0) __syncthreads();
            if (s <= 16) {
                int s2 = s + 2;
                const float* src = (s2 == 18) ? (g_wrp + (size_t)e * 8192)
                    : (g_w2p + (size_t)((e * 9 + s2 % 9) * 128 + (s2 / 9) * 64) * 128);
                float* wn = wb[s2 % 3];
                for (int idx = t; idx < 2048; idx += 256) {
                    int ci = idx >> 5, c4 = (idx & 31) * 4;
                    cpa(s2u(wn + ci * 136 + c4), src + ci * 128 + c4, true);
                }
                CPC; CPW1;                                 // forces W(s+1)
            } else if (s == 17) { CPW0; }                  // forces W18
            if (s == 9) {                                  // xr LDG (use at s18)
#pragma unroll
                for (int i = 0; i < 8; i++) {
                    int idx = i * 256 + t, pix = idx >> 4, c4 = (idx & 15) * 4;
                    int gr = r0 + (pix >> 4), gc = c0 + (pix & 15);
                    xv[i] = *(const float4*)(g_xnhwc +
                        ((size_t)(b * 128 + gr) * 128 + gc) * 64 + c4);
                }
            }
            if (s == 10) {                                 // xr STS into freed bufA
#pragma unroll
                for (int i = 0; i < 8; i++) {
                    int idx = i * 256 + t, pix = idx >> 4, c4 = (idx & 15) * 4;
                    *(float4*)(bufA + pix * 68 + c4) = xv[i];
                }
            }
            if (s < 9) {
                ksteps8<18, 68, 2>(bufA, ((s / 3) * 18 + s % 3) * 68, wb[s % 3],
                                   mbase, nbase, lane, acc);
            } else if (s < 18) {
                int tap = s - 9;
                ksteps8<18, 68, 2>(bufB, ((tap / 3) * 18 + tap % 3) * 68, wb[s % 3],
                                   mbase, nbase, lane, acc);
            } else {
                ksteps8<16, 68, 2>(bufA, 0, wb[s % 3], mbase, nbase, lane, acc);
            }
        }
        float g = gsm[e];
#pragma unroll
        for (int mt = 0; mt < 2; mt++)
#pragma unroll
            for (int nt = 0; nt < 8; nt++) {
                int co = nbase + nt * 8 + (lane & 3) * 2;
                float bb0 = bsm[e * 128 + co], bb1 = bsm[e * 128 + co + 1];
                comb[mt][nt][0] += g * fmaxf(acc[mt][nt][0] + bb0, 0.f);
                comb[mt][nt][1] += g * fmaxf(acc[mt][nt][1] + bb1, 0.f);
                comb[mt][nt][2] += g * fmaxf(acc[mt][nt][2] + bb0, 0.f);
                comb[mt][nt][3] += g * fmaxf(acc[mt][nt][3] + bb1, 0.f);
            }
    }
    // write y
    float* yb = g_y + ((size_t)b << 21);
#pragma unroll
    for (int mt = 0; mt < 2; mt++) {
        int p0 = mbase + mt * 16 + (lane >> 2);
        int py = r0 + (p0 >> 4), px = c0 + (p0 & 15);
#pragma unroll
        for (int nt = 0; nt < 8; nt++) {
            int co = nbase + nt * 8 + (lane & 3) * 2;
            size_t base = ((size_t)py * 128 + px) * 128 + co;
            *(float2*)(yb + base) = make_float2(comb[mt][nt][0], comb[mt][nt][1]);
            *(float2*)(yb + base + 1024) = make_float2(comb[mt][nt][2], comb[mt][nt][3]);
        }
    }
    // deterministic GN partials: per-thread group sums (gl = nt>>1)
    float sp[4] = {}, qp[4] = {};
#pragma unroll
    for (int mt = 0; mt < 2; mt++)
#pragma unroll
        for (int nt = 0; nt < 8; nt++)
#pragma unroll
            for (int j = 0; j < 4; j++) {
                float v = comb[mt][nt][j];
                sp[nt >> 1] += v; qp[nt >> 1] += v * v;
            }
#pragma unroll
    for (int off = 16; off; off >>= 1)
#pragma unroll
        for (int i = 0; i < 4; i++) {
            sp[i] += __shfl_down_sync(0xFFFFFFFFu, sp[i], off);
            qp[i] += __shfl_down_sync(0xFFFFFFFFu, qp[i], off);
        }
    if (lane == 0)
#pragma unroll
        for (int i = 0; i < 4; i++) { wS[w * 4 + i] = sp[i]; wQ[w * 4 + i] = qp[i]; }
    __syncthreads();
    if (t < 8) {
        int par = t >> 2, gl = t & 3;   // groups 0-3 from even warps (nbase 0), 4-7 odd
        float ss = 0.f, qq = 0.f;
#pragma unroll
        for (int k = 0; k < 4; k++) {
            ss += wS[(2 * k + par) * 4 + gl];
            qq += wQ[(2 * k + par) * 4 + gl];
        }
        g_p1[(b * 128 + tile) * 8 + t] = ss;
        g_p2[(b * 128 + tile) * 8 + t] = qq;
    }
}

// ---------------- normalize + NHWC -> NCHW ----------------
__global__ void finalize_kernel(float* __restrict__ out, const float* __restrict__ gamma,
                                const float* __restrict__ beta) {
    extern __shared__ float s[];
    __shared__ float smu[8], sinv[8];
    int b = blockIdx.x >> 7, y = blockIdx.x & 127, t = threadIdx.x;
    if (t < 8) {
        float ss = 0.f, qq = 0.f;
        for (int tile = 0; tile < 128; tile++) {
            ss += g_p1[(b * 128 + tile) * 8 + t];
            qq += g_p2[(b * 128 + tile) * 8 + t];
        }
        float mu = ss * (1.f / 262144.f);
        smu[t] = mu;
        sinv[t] = rsqrtf(qq * (1.f / 262144.f) - mu * mu + 1e-5f);
    }
    const float* yb = g_y + (((size_t)b * 16384) + y * 128) * 128;
#pragma unroll 4
    for (int i = 0; i < 64; i++) {
        int idx = i * 256 + t, xx = idx >> 7, co = idx & 127;
        s[xx * 129 + co] = yb[xx * 128 + co];
    }
    __syncthreads();
#pragma unroll 4
    for (int i = 0; i < 64; i++) {
        int idx = i * 256 + t, co = idx >> 7, xx = idx & 127, g = co >> 4;
        out[(((size_t)b * 128 + co) * 128 + y) * 128 + xx] =
            (s[xx * 129 + co] - smu[g]) * sinv[g] * gamma[co] + beta[co];
    }
}

extern "C" void kernel_launch(void* const* d_in, const int* in_sizes, int n_in,
                              void* d_out, int out_size) {
    const float* x   = (const float*)d_in[0];
    const float* W1  = (const float*)d_in[1];
    const float* b1  = (const float*)d_in[2];
    const float* W2  = (const float*)d_in[3];
    const float* b2  = (const float*)d_in[4];
    const float* Wr  = (const float*)d_in[5];
    const float* br  = (const float*)d_in[6];
    const float* Rw1 = (const float*)d_in[7];
    const float* Rb1 = (const float*)d_in[8];
    const float* Rw2 = (const float*)d_in[9];
    const float* Rb2 = (const float*)d_in[10];
    const float* gamma = (const float*)d_in[11];
    const float* beta  = (const float*)d_in[12];
    float* out = (float*)d_out;

    cudaFuncSetAttribute(conv1_kernel, cudaFuncAttributeMaxDynamicSharedMemorySize, 193088);
    cudaFuncSetAttribute(conv2_kernel, cudaFuncAttributeMaxDynamicSharedMemorySize, 206752);
    cudaFuncSetAttribute(finalize_kernel, cudaFuncAttributeMaxDynamicSharedMemorySize, 66048);

    router_kernel<<<512, 128>>>(x, Rw1, Rb1, Rw2, Rb2);
    transpose_kernel<<<1024, 256>>>(x);
    prep_kernel<<<7168, 256>>>(W1, W2, Wr);
    conv1_kernel<<<dim3(64, 8, 8), 256, 193088>>>(b1);
    conv2_kernel<<<dim3(128, 8), 256, 206752>>>(b2, br);
    finalize_kernel<<<1024, 256, 66048>>>(out, gamma, beta);
}